// round 3
// baseline (speedup 1.0000x reference)
#include <cuda_runtime.h>
#include <math.h>

#define NSC   48
#define RMAX  11
#define NCTA  (3*NSC)

__device__ float4 g_gw0p[3*76*64];
__device__ float4 g_gw1p[3*128*64];
__device__ float  g_Wa[6*64*64];
__device__ float  g_ba[6*64];
__device__ float  g_outs[3ull*512*512*64];

__device__ __forceinline__ float sigmf(float v){ return 1.0f/(1.0f + __expf(-v)); }

__global__ void pack_gw_kernel(const float* __restrict__ gw0, const float* __restrict__ gw1){
    int i = blockIdx.x*blockDim.x + threadIdx.x;
    float* p0 = (float*)g_gw0p;
    float* p1 = (float*)g_gw1p;
    if (i < 3*76*256){
        int s = i/(76*256), rem = i%(76*256), k = rem/256, j = rem%256;
        p0[(s*76 + k)*256 + ((j&63)<<2) + (j>>6)] = gw0[i];
    }
    if (i < 3*128*256){
        int s = i/(128*256), rem = i%(128*256), k = rem/256, j = rem%256;
        p1[(s*128 + k)*256 + ((j&63)<<2) + (j>>6)] = gw1[i];
    }
}

__global__ void compute_wa_kernel(const float* __restrict__ mi_w, const float* __restrict__ mi_b,
                                  const float* __restrict__ mo_w, const float* __restrict__ mo_b){
    int sl = blockIdx.x;
    const float* miw = mi_w + (size_t)sl*64*192;
    const float* mow = mo_w + (size_t)sl*64*64;
    for (int idx = threadIdx.x; idx < 64*64; idx += blockDim.x){
        int k = idx>>6, n = idx&63;
        float acc = 0.f;
        #pragma unroll 8
        for (int j=0;j<64;j++) acc += miw[k*192 + 128 + j] * mow[j*64 + n];
        g_Wa[sl*4096 + k*64 + n] = acc;
    }
    if (threadIdx.x < 64){
        int n = threadIdx.x;
        float acc = mo_b[sl*64 + n];
        #pragma unroll 8
        for (int j=0;j<64;j++) acc += mi_b[sl*192 + 128 + j] * mow[j*64 + n];
        g_ba[sl*64 + n] = acc;
    }
}

__global__ void __launch_bounds__(256, 1) xlstm_kernel(
    const float* __restrict__ x,
    const float* __restrict__ gb0, const float* __restrict__ gb1,
    const float* __restrict__ w1,  const float* __restrict__ b1,
    const float* __restrict__ w2,  const float* __restrict__ b2,
    const float* __restrict__ lag, const float* __restrict__ lab,
    const float* __restrict__ logw,const float* __restrict__ lob,
    const float* __restrict__ rw0, const float* __restrict__ rb0,
    const float* __restrict__ rw1, const float* __restrict__ rb1)
{
    const int cta = blockIdx.x;
    const int s   = cta / NSC;
    const int ci  = cta % NSC;
    const int base  = (ci < 32) ? ci*11 : 352 + (ci-32)*10;
    const int nrows = (ci < 32) ? 11 : 10;
    const int tid  = threadIdx.x;
    const int m    = tid & 63;
    const int rg   = tid >> 6;
    const int lane = tid & 31;
    const int wrp  = tid >> 5;
    const int n2   = tid & 127;
    const int rg2  = tid >> 7;

    __shared__ float sh_h0[RMAX][64], sh_h1[RMAX][64];
    __shared__ float sh_x[RMAX][12];
    __shared__ float sh_ht[RMAX][64];
    __shared__ float sh_a[RMAX][64];
    __shared__ float sh_t1[RMAX][128];
    __shared__ float sh_y[RMAX][64];
    __shared__ float sh_inp[RMAX][64];
    __shared__ float sh_stat[RMAX][2];
    __shared__ float sb_gb0[256], sb_gb1[256];
    __shared__ float sb_b1[2][128], sb_b2[2][64], sb_ba[2][64];
    __shared__ float sb_lag[2][64], sb_lab[2][64], sb_log[2][64], sb_lob[2][64];
    __shared__ float sb_rb0[64], sb_rb1[64];

    for (int i = tid; i < RMAX*64; i += 256){ ((float*)sh_h0)[i] = 0.f; ((float*)sh_h1)[i] = 0.f; }
    sb_gb0[tid] = gb0[s*256 + tid];
    sb_gb1[tid] = gb1[s*256 + tid];
    if (tid < 128){
        sb_b1[0][tid] = b1[(s*2+0)*128 + tid];
        sb_b1[1][tid] = b1[(s*2+1)*128 + tid];
    }
    if (tid < 64){
        #pragma unroll
        for (int l=0;l<2;l++){
            sb_b2[l][tid]  = b2 [(s*2+l)*64 + tid];
            sb_ba[l][tid]  = g_ba[(s*2+l)*64 + tid];
            sb_lag[l][tid] = lag[(s*2+l)*64 + tid];
            sb_lab[l][tid] = lab[(s*2+l)*64 + tid];
            sb_log[l][tid] = logw[(s*2+l)*64 + tid];
            sb_lob[l][tid] = lob[(s*2+l)*64 + tid];
        }
        sb_rb0[tid] = rb0[s*64 + tid];
        sb_rb1[tid] = rb1[s*64 + tid];
    }
    __syncthreads();

    int myr[3]; int nmy = 0;
    #pragma unroll
    for (int q=0;q<3;q++){ int r = rg + 4*q; myr[q] = (r < nrows) ? r : (nrows-1); if (r < nrows) nmy = q+1; }
    int myr2[6]; int nmy2 = 0;
    #pragma unroll
    for (int q=0;q<6;q++){ int r = rg2 + 2*q; myr2[q] = (r < nrows) ? r : (nrows-1); if (r < nrows) nmy2 = q+1; }

    float c0r[3] = {0.f,0.f,0.f}, c1r[3] = {0.f,0.f,0.f};

    const float4* gw0p = g_gw0p + (size_t)s*76*64;
    const float4* gw1p = g_gw1p + (size_t)s*128*64;
    const float* Wa_l0 = g_Wa + (size_t)(s*2+0)*4096;
    const float* Wa_l1 = g_Wa + (size_t)(s*2+1)*4096;
    const float* w1_l0 = w1 + (size_t)(s*2+0)*64*128;
    const float* w1_l1 = w1 + (size_t)(s*2+1)*64*128;
    const float* w2_l0 = w2 + (size_t)(s*2+0)*128*64;
    const float* w2_l1 = w2 + (size_t)(s*2+1)*128*64;
    const float* rw0s  = rw0 + (size_t)s*12*64;
    const float* rw1s  = rw1 + (size_t)s*64*64;

    const int Li  = (s==0) ? 170 : (s==1 ? 512 : 256);
    const int st0 = (s==0) ? 342 : (s==1 ? 0   : 256);
    const float scf = (float)Li / 512.0f;

    float* outbase = g_outs + ((size_t)s*512 + base)*512*64;

    auto ln_pass = [&](){
        for (int r = wrp; r < nrows; r += 8){
            float v0 = sh_y[r][lane], v1 = sh_y[r][lane+32];
            float sm = v0 + v1, sq = v0*v0 + v1*v1;
            #pragma unroll
            for (int o=16;o;o>>=1){
                sm += __shfl_xor_sync(0xffffffffu, sm, o);
                sq += __shfl_xor_sync(0xffffffffu, sq, o);
            }
            if (lane == 0){
                float mean = sm * 0.015625f;
                float var  = sq * 0.015625f - mean*mean;
                sh_stat[r][0] = mean;
                sh_stat[r][1] = rsqrtf(var + 1e-5f);
            }
        }
    };

    auto attn_ff_ln = [&](const float* Wap, const float* w1p, const float* w2p, int l,
                          float (*hstate)[64], float* hn_out){
        {
            float aa[3];
            #pragma unroll
            for (int q=0;q<3;q++) aa[q] = sb_ba[l][m];
            #pragma unroll 8
            for (int k=0;k<64;k++){
                float wv = Wap[k*64 + m];
                #pragma unroll
                for (int q=0;q<3;q++) aa[q] += sh_ht[myr[q]][k] * wv;
            }
            #pragma unroll
            for (int q=0;q<3;q++) if (q < nmy) sh_a[myr[q]][m] = aa[q];
        }
        __syncthreads();
        {
            float ta[6];
            #pragma unroll
            for (int q=0;q<6;q++) ta[q] = sb_b1[l][n2];
            #pragma unroll 8
            for (int k=0;k<64;k++){
                float wv = w1p[k*128 + n2];
                #pragma unroll
                for (int q=0;q<6;q++) ta[q] += sh_a[myr2[q]][k] * wv;
            }
            #pragma unroll
            for (int q=0;q<6;q++){
                float v = ta[q];
                float ge = 0.5f * v * (1.0f + erff(v * 0.7071067811865475f));
                if (q < nmy2) sh_t1[myr2[q]][n2] = ge;
            }
        }
        __syncthreads();
        {
            float ta[3];
            #pragma unroll
            for (int q=0;q<3;q++) ta[q] = sb_b2[l][m];
            #pragma unroll 8
            for (int k=0;k<128;k++){
                float wv = w2p[k*64 + m];
                #pragma unroll
                for (int q=0;q<3;q++) ta[q] += sh_t1[myr[q]][k] * wv;
            }
            #pragma unroll
            for (int q=0;q<3;q++) if (q < nmy) sh_y[myr[q]][m] = ta[q];
        }
        __syncthreads();
        ln_pass();
        __syncthreads();
        #pragma unroll
        for (int q=0;q<3;q++){
            int r = myr[q];
            float v  = sh_y[r][m];
            float ln = (v - sh_stat[r][0]) * sh_stat[r][1] * sb_lag[l][m] + sb_lab[l][m];
            float yv = ln + hstate[r][m];
            if (q < nmy) sh_y[r][m] = yv;
        }
        __syncthreads();
        ln_pass();
        __syncthreads();
        #pragma unroll
        for (int q=0;q<3;q++){
            int r = myr[q];
            float yv = sh_y[r][m];
            float hn = (yv - sh_stat[r][0]) * sh_stat[r][1] * sb_log[l][m] + sb_lob[l][m];
            hn_out[q] = hn;
            if (q < nmy) hstate[r][m] = hn;
        }
    };

    for (int t=0; t<512; t++){
        float srcf = fmaxf((t + 0.5f) * scf - 0.5f, 0.0f);
        int i0 = (int)srcf;
        if (i0 > Li-1) i0 = Li-1;
        int i1 = min(i0+1, Li-1);
        float wu = srcf - (float)i0;
        if (tid < nrows*12){
            int r = tid/12, k = tid%12;
            const float* xb = x + ((size_t)(base+r)*512 + st0)*12;
            float v0 = xb[i0*12 + k], v1 = xb[i1*12 + k];
            sh_x[r][k] = v0*(1.0f - wu) + v1*wu;
        }
        __syncthreads();

        // layer 0 gates
        {
            float af[3], ai[3], ag[3], ao[3];
            #pragma unroll
            for (int q=0;q<3;q++){ af[q]=sb_gb0[m]; ai[q]=sb_gb0[64+m]; ag[q]=sb_gb0[128+m]; ao[q]=sb_gb0[192+m]; }
            #pragma unroll
            for (int k=0;k<12;k++){
                float4 wv = gw0p[k*64 + m];
                #pragma unroll
                for (int q=0;q<3;q++){
                    float z = sh_x[myr[q]][k];
                    af[q] += z*wv.x; ai[q] += z*wv.y; ag[q] += z*wv.z; ao[q] += z*wv.w;
                }
            }
            #pragma unroll 8
            for (int k=0;k<64;k++){
                float4 wv = gw0p[(12+k)*64 + m];
                #pragma unroll
                for (int q=0;q<3;q++){
                    float z = sh_h0[myr[q]][k];
                    af[q] += z*wv.x; ai[q] += z*wv.y; ag[q] += z*wv.z; ao[q] += z*wv.w;
                }
            }
            #pragma unroll
            for (int q=0;q<3;q++){
                float cn = sigmf(af[q])*c0r[q] + sigmf(ai[q])*tanhf(ag[q]);
                float ht = sigmf(ao[q])*tanhf(cn);
                if (q < nmy){ c0r[q] = cn; sh_ht[myr[q]][m] = ht; }
            }
        }
        __syncthreads();

        float h0n[3];
        attn_ff_ln(Wa_l0, w1_l0, w2_l0, 0, sh_h0, h0n);

        #pragma unroll
        for (int q=0;q<3;q++){
            int r = myr[q];
            float acc = h0n[q] + sb_rb0[m];
            #pragma unroll
            for (int k=0;k<12;k++) acc += sh_x[r][k] * rw0s[k*64 + m];
            if (q < nmy) sh_inp[r][m] = acc;
        }
        __syncthreads();

        // layer 1 gates
        {
            float af[3], ai[3], ag[3], ao[3];
            #pragma unroll
            for (int q=0;q<3;q++){ af[q]=sb_gb1[m]; ai[q]=sb_gb1[64+m]; ag[q]=sb_gb1[128+m]; ao[q]=sb_gb1[192+m]; }
            #pragma unroll 8
            for (int k=0;k<64;k++){
                float4 wv = gw1p[k*64 + m];
                #pragma unroll
                for (int q=0;q<3;q++){
                    float z = sh_inp[myr[q]][k];
                    af[q] += z*wv.x; ai[q] += z*wv.y; ag[q] += z*wv.z; ao[q] += z*wv.w;
                }
            }
            #pragma unroll 8
            for (int k=0;k<64;k++){
                float4 wv = gw1p[(64+k)*64 + m];
                #pragma unroll
                for (int q=0;q<3;q++){
                    float z = sh_h1[myr[q]][k];
                    af[q] += z*wv.x; ai[q] += z*wv.y; ag[q] += z*wv.z; ao[q] += z*wv.w;
                }
            }
            #pragma unroll
            for (int q=0;q<3;q++){
                float cn = sigmf(af[q])*c1r[q] + sigmf(ai[q])*tanhf(ag[q]);
                float ht = sigmf(ao[q])*tanhf(cn);
                if (q < nmy){ c1r[q] = cn; sh_ht[myr[q]][m] = ht; }
            }
        }
        __syncthreads();

        float h1n[3];
        attn_ff_ln(Wa_l1, w1_l1, w2_l1, 1, sh_h1, h1n);

        #pragma unroll
        for (int q=0;q<3;q++){
            int r = myr[q];
            float acc = h1n[q] + sb_rb1[m];
            #pragma unroll 8
            for (int k=0;k<64;k++) acc += sh_inp[r][k] * rw1s[k*64 + m];
            if (q < nmy) outbase[((size_t)r*512 + t)*64 + m] = acc;
        }
        __syncthreads();
    }
}

__global__ void merge_kernel(const float* __restrict__ attn_w, float* __restrict__ out){
    int warp = (blockIdx.x*blockDim.x + threadIdx.x) >> 5;
    int lane = threadIdx.x & 31;
    if (warp >= 512*512) return;
    const size_t SS = 512ull*512*64;
    const float* p = g_outs + (size_t)warp*64;
    float aw0 = attn_w[lane], aw1 = attn_w[lane+32];
    float v0[3], v1[3], sc[3];
    #pragma unroll
    for (int si=0; si<3; si++){
        v0[si] = p[si*SS + lane];
        v1[si] = p[si*SS + lane + 32];
        float d = v0[si]*aw0 + v1[si]*aw1;
        #pragma unroll
        for (int o=16;o;o>>=1) d += __shfl_xor_sync(0xffffffffu, d, o);
        sc[si] = d;
    }
    float mx = fmaxf(sc[0], fmaxf(sc[1], sc[2]));
    float e0 = __expf(sc[0]-mx), e1 = __expf(sc[1]-mx), e2 = __expf(sc[2]-mx);
    float inv = 1.0f/(e0+e1+e2);
    float wt0 = e0*inv, wt1 = e1*inv, wt2 = e2*inv;
    out[(size_t)warp*64 + lane]      = v0[0]*wt0 + v0[1]*wt1 + v0[2]*wt2;
    out[(size_t)warp*64 + lane + 32] = v1[0]*wt0 + v1[1]*wt1 + v1[2]*wt2;
}

extern "C" void kernel_launch(void* const* d_in, const int* in_sizes, int n_in,
                              void* d_out, int out_size){
    const float* x     = (const float*)d_in[0];
    const float* gw0   = (const float*)d_in[1];
    const float* gb0   = (const float*)d_in[2];
    const float* gw1   = (const float*)d_in[3];
    const float* gb1   = (const float*)d_in[4];
    const float* mi_w  = (const float*)d_in[5];
    const float* mi_b  = (const float*)d_in[6];
    const float* mo_w  = (const float*)d_in[7];
    const float* mo_b  = (const float*)d_in[8];
    const float* w1    = (const float*)d_in[9];
    const float* b1    = (const float*)d_in[10];
    const float* w2    = (const float*)d_in[11];
    const float* b2    = (const float*)d_in[12];
    const float* lag   = (const float*)d_in[13];
    const float* lab   = (const float*)d_in[14];
    const float* logw  = (const float*)d_in[15];
    const float* lob   = (const float*)d_in[16];
    const float* rw0   = (const float*)d_in[17];
    const float* rb0   = (const float*)d_in[18];
    const float* rw1   = (const float*)d_in[19];
    const float* rb1   = (const float*)d_in[20];
    const float* attnw = (const float*)d_in[21];
    float* out = (float*)d_out;

    pack_gw_kernel<<<(3*128*256 + 255)/256, 256>>>(gw0, gw1);
    compute_wa_kernel<<<6, 256>>>(mi_w, mi_b, mo_w, mo_b);
    xlstm_kernel<<<NCTA, 256>>>(x, gb0, gb1, w1, b1, w2, b2,
                                lag, lab, logw, lob, rw0, rb0, rw1, rb1);
    merge_kernel<<<(512*512*32 + 255)/256, 256>>>(attnw, out);
}

// round 4
// speedup vs baseline: 1.0660x; 1.0660x over previous
#include <cuda_runtime.h>
#include <math.h>

#define NSC   48
#define RMAX  11
#define NCTA  (3*NSC)
#define T     384

__device__ float4 g_gw0p[3*76*64];
__device__ float4 g_gw1p[3*128*64];
__device__ float  g_Wa[6*64*64];
__device__ float  g_ba[6*64];
__device__ float  g_outs[3ull*512*512*64];

__device__ __forceinline__ float sigmf(float v){
    return __fdividef(1.0f, 1.0f + __expf(-v));
}
__device__ __forceinline__ float tanhfast(float v){
    return 1.0f - __fdividef(2.0f, __expf(2.0f*v) + 1.0f);
}

__global__ void pack_gw_kernel(const float* __restrict__ gw0, const float* __restrict__ gw1){
    int i = blockIdx.x*blockDim.x + threadIdx.x;
    float* p0 = (float*)g_gw0p;
    float* p1 = (float*)g_gw1p;
    if (i < 3*76*256){
        int s = i/(76*256), rem = i%(76*256), k = rem/256, j = rem%256;
        p0[(s*76 + k)*256 + ((j&63)<<2) + (j>>6)] = gw0[i];
    }
    if (i < 3*128*256){
        int s = i/(128*256), rem = i%(128*256), k = rem/256, j = rem%256;
        p1[(s*128 + k)*256 + ((j&63)<<2) + (j>>6)] = gw1[i];
    }
}

__global__ void compute_wa_kernel(const float* __restrict__ mi_w, const float* __restrict__ mi_b,
                                  const float* __restrict__ mo_w, const float* __restrict__ mo_b){
    int sl = blockIdx.x;
    const float* miw = mi_w + (size_t)sl*64*192;
    const float* mow = mo_w + (size_t)sl*64*64;
    for (int idx = threadIdx.x; idx < 64*64; idx += blockDim.x){
        int k = idx>>6, n = idx&63;
        float acc = 0.f;
        #pragma unroll 8
        for (int j=0;j<64;j++) acc += miw[k*192 + 128 + j] * mow[j*64 + n];
        g_Wa[sl*4096 + k*64 + n] = acc;
    }
    if (threadIdx.x < 64){
        int n = threadIdx.x;
        float acc = mo_b[sl*64 + n];
        #pragma unroll 8
        for (int j=0;j<64;j++) acc += mi_b[sl*192 + 128 + j] * mow[j*64 + n];
        g_ba[sl*64 + n] = acc;
    }
}

__global__ void __launch_bounds__(T, 1) xlstm_kernel(
    const float* __restrict__ x,
    const float* __restrict__ gb0, const float* __restrict__ gb1,
    const float* __restrict__ w1,  const float* __restrict__ b1,
    const float* __restrict__ w2,  const float* __restrict__ b2,
    const float* __restrict__ lag, const float* __restrict__ lab,
    const float* __restrict__ logw,const float* __restrict__ lob,
    const float* __restrict__ rw0, const float* __restrict__ rb0,
    const float* __restrict__ rw1, const float* __restrict__ rb1)
{
    const int cta = blockIdx.x;
    const int s   = cta / NSC;
    const int ci  = cta % NSC;
    const int base  = (ci < 32) ? ci*11 : 352 + (ci-32)*10;
    const int nrows = (ci < 32) ? 11 : 10;
    const int tid  = threadIdx.x;
    const int m    = tid & 63;
    const int rg   = tid >> 6;     // 0..5
    const int lane = tid & 31;
    const int wrp  = tid >> 5;     // 0..11
    const int n2   = tid & 127;
    const int rg2  = tid >> 7;     // 0..2

    __shared__ float sh_h0[RMAX][64], sh_h1[RMAX][64];
    __shared__ float sh_x[RMAX][12];
    __shared__ float sh_ht[RMAX][64];
    __shared__ float sh_a[RMAX][64];
    __shared__ float sh_t1[RMAX][128];
    __shared__ float sh_y[RMAX][64];
    __shared__ float sh_inp[RMAX][64];
    __shared__ float sh_stat[RMAX][2];
    __shared__ float sb_gb0[256], sb_gb1[256];
    __shared__ float sb_b1[2][128], sb_b2[2][64], sb_ba[2][64];
    __shared__ float sb_lag[2][64], sb_lab[2][64], sb_log[2][64], sb_lob[2][64];
    __shared__ float sb_rb0[64], sb_rb1[64];

    for (int i = tid; i < RMAX*64; i += T){ ((float*)sh_h0)[i] = 0.f; ((float*)sh_h1)[i] = 0.f; }
    if (tid < 256){
        sb_gb0[tid] = gb0[s*256 + tid];
        sb_gb1[tid] = gb1[s*256 + tid];
    }
    if (tid < 128){
        sb_b1[0][tid] = b1[(s*2+0)*128 + tid];
        sb_b1[1][tid] = b1[(s*2+1)*128 + tid];
    }
    if (tid < 64){
        #pragma unroll
        for (int l=0;l<2;l++){
            sb_b2[l][tid]  = b2 [(s*2+l)*64 + tid];
            sb_ba[l][tid]  = g_ba[(s*2+l)*64 + tid];
            sb_lag[l][tid] = lag[(s*2+l)*64 + tid];
            sb_lab[l][tid] = lab[(s*2+l)*64 + tid];
            sb_log[l][tid] = logw[(s*2+l)*64 + tid];
            sb_lob[l][tid] = lob[(s*2+l)*64 + tid];
        }
        sb_rb0[tid] = rb0[s*64 + tid];
        sb_rb1[tid] = rb1[s*64 + tid];
    }
    __syncthreads();

    // rows per thread: 64-wide stages (6 groups x up to 2 rows)
    int myr[2]; int nmy = 0;
    #pragma unroll
    for (int q=0;q<2;q++){ int r = rg + 6*q; myr[q] = (r < nrows) ? r : (nrows-1); if (r < nrows) nmy = q+1; }
    // 128-wide stage (3 groups x up to 4 rows)
    int myr2[4]; int nmy2 = 0;
    #pragma unroll
    for (int q=0;q<4;q++){ int r = rg2 + 3*q; myr2[q] = (r < nrows) ? r : (nrows-1); if (r < nrows) nmy2 = q+1; }

    float c0r[2] = {0.f,0.f}, c1r[2] = {0.f,0.f};

    const float4* gw0p = g_gw0p + (size_t)s*76*64;
    const float4* gw1p = g_gw1p + (size_t)s*128*64;
    const float* Wa_l0 = g_Wa + (size_t)(s*2+0)*4096;
    const float* Wa_l1 = g_Wa + (size_t)(s*2+1)*4096;
    const float* w1_l0 = w1 + (size_t)(s*2+0)*64*128;
    const float* w1_l1 = w1 + (size_t)(s*2+1)*64*128;
    const float* w2_l0 = w2 + (size_t)(s*2+0)*128*64;
    const float* w2_l1 = w2 + (size_t)(s*2+1)*128*64;
    const float* rw0s  = rw0 + (size_t)s*12*64;
    const float* rw1s  = rw1 + (size_t)s*64*64;

    const int Li  = (s==0) ? 170 : (s==1 ? 512 : 256);
    const int st0 = (s==0) ? 342 : (s==1 ? 0   : 256);
    const float scf = (float)Li / 512.0f;

    float* outbase = g_outs + ((size_t)s*512 + base)*512*64;

    auto ln_pass = [&](){
        if (wrp < nrows){
            int r = wrp;
            float v0 = sh_y[r][lane], v1 = sh_y[r][lane+32];
            float sm = v0 + v1, sq = v0*v0 + v1*v1;
            #pragma unroll
            for (int o=16;o;o>>=1){
                sm += __shfl_xor_sync(0xffffffffu, sm, o);
                sq += __shfl_xor_sync(0xffffffffu, sq, o);
            }
            if (lane == 0){
                float mean = sm * 0.015625f;
                float var  = sq * 0.015625f - mean*mean;
                sh_stat[r][0] = mean;
                sh_stat[r][1] = rsqrtf(var + 1e-5f);
            }
        }
    };

    auto attn_ff_ln = [&](const float* Wap, const float* w1p, const float* w2p, int l,
                          float (*hstate)[64], float* hn_out){
        {
            float aa[2];
            #pragma unroll
            for (int q=0;q<2;q++) aa[q] = sb_ba[l][m];
            #pragma unroll 8
            for (int k=0;k<64;k++){
                float wv = Wap[k*64 + m];
                #pragma unroll
                for (int q=0;q<2;q++) aa[q] += sh_ht[myr[q]][k] * wv;
            }
            #pragma unroll
            for (int q=0;q<2;q++) if (q < nmy) sh_a[myr[q]][m] = aa[q];
        }
        __syncthreads();
        {
            float ta[4];
            #pragma unroll
            for (int q=0;q<4;q++) ta[q] = sb_b1[l][n2];
            #pragma unroll 8
            for (int k=0;k<64;k++){
                float wv = w1p[k*128 + n2];
                #pragma unroll
                for (int q=0;q<4;q++) ta[q] += sh_a[myr2[q]][k] * wv;
            }
            #pragma unroll
            for (int q=0;q<4;q++){
                float v = ta[q];
                float ge = 0.5f * v * (1.0f + erff(v * 0.7071067811865475f));
                if (q < nmy2) sh_t1[myr2[q]][n2] = ge;
            }
        }
        __syncthreads();
        {
            float ta[2];
            #pragma unroll
            for (int q=0;q<2;q++) ta[q] = sb_b2[l][m];
            #pragma unroll 8
            for (int k=0;k<128;k++){
                float wv = w2p[k*64 + m];
                #pragma unroll
                for (int q=0;q<2;q++) ta[q] += sh_t1[myr[q]][k] * wv;
            }
            #pragma unroll
            for (int q=0;q<2;q++) if (q < nmy) sh_y[myr[q]][m] = ta[q];
        }
        __syncthreads();
        ln_pass();
        __syncthreads();
        #pragma unroll
        for (int q=0;q<2;q++){
            int r = myr[q];
            float v  = sh_y[r][m];
            float ln = (v - sh_stat[r][0]) * sh_stat[r][1] * sb_lag[l][m] + sb_lab[l][m];
            float yv = ln + hstate[r][m];
            if (q < nmy) sh_y[r][m] = yv;
        }
        __syncthreads();
        ln_pass();
        __syncthreads();
        #pragma unroll
        for (int q=0;q<2;q++){
            int r = myr[q];
            float yv = sh_y[r][m];
            float hn = (yv - sh_stat[r][0]) * sh_stat[r][1] * sb_log[l][m] + sb_lob[l][m];
            hn_out[q] = hn;
            if (q < nmy) hstate[r][m] = hn;
        }
    };

    for (int t=0; t<512; t++){
        float srcf = fmaxf((t + 0.5f) * scf - 0.5f, 0.0f);
        int i0 = (int)srcf;
        if (i0 > Li-1) i0 = Li-1;
        int i1 = min(i0+1, Li-1);
        float wu = srcf - (float)i0;
        if (tid < nrows*12){
            int r = tid/12, k = tid%12;
            const float* xb = x + ((size_t)(base+r)*512 + st0)*12;
            float v0 = xb[i0*12 + k], v1 = xb[i1*12 + k];
            sh_x[r][k] = v0*(1.0f - wu) + v1*wu;
        }
        __syncthreads();

        // ---- layer 0 gates ----
        {
            float af[2], ai[2], ag[2], ao[2];
            #pragma unroll
            for (int q=0;q<2;q++){ af[q]=sb_gb0[m]; ai[q]=sb_gb0[64+m]; ag[q]=sb_gb0[128+m]; ao[q]=sb_gb0[192+m]; }
            #pragma unroll
            for (int k=0;k<12;k++){
                float4 wv = gw0p[k*64 + m];
                #pragma unroll
                for (int q=0;q<2;q++){
                    float z = sh_x[myr[q]][k];
                    af[q] += z*wv.x; ai[q] += z*wv.y; ag[q] += z*wv.z; ao[q] += z*wv.w;
                }
            }
            #pragma unroll 8
            for (int k=0;k<64;k++){
                float4 wv = gw0p[(12+k)*64 + m];
                #pragma unroll
                for (int q=0;q<2;q++){
                    float z = sh_h0[myr[q]][k];
                    af[q] += z*wv.x; ai[q] += z*wv.y; ag[q] += z*wv.z; ao[q] += z*wv.w;
                }
            }
            #pragma unroll
            for (int q=0;q<2;q++){
                float cn = sigmf(af[q])*c0r[q] + sigmf(ai[q])*tanhfast(ag[q]);
                float ht = sigmf(ao[q])*tanhfast(cn);
                if (q < nmy){ c0r[q] = cn; sh_ht[myr[q]][m] = ht; }
            }
        }
        __syncthreads();

        float h0n[2];
        attn_ff_ln(Wa_l0, w1_l0, w2_l0, 0, sh_h0, h0n);

        #pragma unroll
        for (int q=0;q<2;q++){
            int r = myr[q];
            float acc = h0n[q] + sb_rb0[m];
            #pragma unroll
            for (int k=0;k<12;k++) acc += sh_x[r][k] * rw0s[k*64 + m];
            if (q < nmy) sh_inp[r][m] = acc;
        }
        __syncthreads();

        // ---- layer 1 gates ----
        {
            float af[2], ai[2], ag[2], ao[2];
            #pragma unroll
            for (int q=0;q<2;q++){ af[q]=sb_gb1[m]; ai[q]=sb_gb1[64+m]; ag[q]=sb_gb1[128+m]; ao[q]=sb_gb1[192+m]; }
            #pragma unroll 8
            for (int k=0;k<64;k++){
                float4 wv = gw1p[k*64 + m];
                #pragma unroll
                for (int q=0;q<2;q++){
                    float z = sh_inp[myr[q]][k];
                    af[q] += z*wv.x; ai[q] += z*wv.y; ag[q] += z*wv.z; ao[q] += z*wv.w;
                }
            }
            #pragma unroll 8
            for (int k=0;k<64;k++){
                float4 wv = gw1p[(64+k)*64 + m];
                #pragma unroll
                for (int q=0;q<2;q++){
                    float z = sh_h1[myr[q]][k];
                    af[q] += z*wv.x; ai[q] += z*wv.y; ag[q] += z*wv.z; ao[q] += z*wv.w;
                }
            }
            #pragma unroll
            for (int q=0;q<2;q++){
                float cn = sigmf(af[q])*c1r[q] + sigmf(ai[q])*tanhfast(ag[q]);
                float ht = sigmf(ao[q])*tanhfast(cn);
                if (q < nmy){ c1r[q] = cn; sh_ht[myr[q]][m] = ht; }
            }
        }
        __syncthreads();

        float h1n[2];
        attn_ff_ln(Wa_l1, w1_l1, w2_l1, 1, sh_h1, h1n);

        #pragma unroll
        for (int q=0;q<2;q++){
            int r = myr[q];
            float acc = h1n[q] + sb_rb1[m];
            #pragma unroll 8
            for (int k=0;k<64;k++) acc += sh_inp[r][k] * rw1s[k*64 + m];
            if (q < nmy) outbase[((size_t)r*512 + t)*64 + m] = acc;
        }
        __syncthreads();
    }
}

__global__ void merge_kernel(const float* __restrict__ attn_w, float* __restrict__ out){
    int warp = (blockIdx.x*blockDim.x + threadIdx.x) >> 5;
    int lane = threadIdx.x & 31;
    if (warp >= 512*512) return;
    const size_t SS = 512ull*512*64;
    const float* p = g_outs + (size_t)warp*64;
    float aw0 = attn_w[lane], aw1 = attn_w[lane+32];
    float v0[3], v1[3], sc[3];
    #pragma unroll
    for (int si=0; si<3; si++){
        v0[si] = p[si*SS + lane];
        v1[si] = p[si*SS + lane + 32];
        float d = v0[si]*aw0 + v1[si]*aw1;
        #pragma unroll
        for (int o=16;o;o>>=1) d += __shfl_xor_sync(0xffffffffu, d, o);
        sc[si] = d;
    }
    float mx = fmaxf(sc[0], fmaxf(sc[1], sc[2]));
    float e0 = __expf(sc[0]-mx), e1 = __expf(sc[1]-mx), e2 = __expf(sc[2]-mx);
    float inv = __fdividef(1.0f, e0+e1+e2);
    float wt0 = e0*inv, wt1 = e1*inv, wt2 = e2*inv;
    out[(size_t)warp*64 + lane]      = v0[0]*wt0 + v0[1]*wt1 + v0[2]*wt2;
    out[(size_t)warp*64 + lane + 32] = v1[0]*wt0 + v1[1]*wt1 + v1[2]*wt2;
}

extern "C" void kernel_launch(void* const* d_in, const int* in_sizes, int n_in,
                              void* d_out, int out_size){
    const float* x     = (const float*)d_in[0];
    const float* gw0   = (const float*)d_in[1];
    const float* gb0   = (const float*)d_in[2];
    const float* gw1   = (const float*)d_in[3];
    const float* gb1   = (const float*)d_in[4];
    const float* mi_w  = (const float*)d_in[5];
    const float* mi_b  = (const float*)d_in[6];
    const float* mo_w  = (const float*)d_in[7];
    const float* mo_b  = (const float*)d_in[8];
    const float* w1    = (const float*)d_in[9];
    const float* b1    = (const float*)d_in[10];
    const float* w2    = (const float*)d_in[11];
    const float* b2    = (const float*)d_in[12];
    const float* lag   = (const float*)d_in[13];
    const float* lab   = (const float*)d_in[14];
    const float* logw  = (const float*)d_in[15];
    const float* lob   = (const float*)d_in[16];
    const float* rw0   = (const float*)d_in[17];
    const float* rb0   = (const float*)d_in[18];
    const float* rw1   = (const float*)d_in[19];
    const float* rb1   = (const float*)d_in[20];
    const float* attnw = (const float*)d_in[21];
    float* out = (float*)d_out;

    pack_gw_kernel<<<(3*128*256 + 255)/256, 256>>>(gw0, gw1);
    compute_wa_kernel<<<6, 256>>>(mi_w, mi_b, mo_w, mo_b);
    xlstm_kernel<<<NCTA, T>>>(x, gb0, gb1, w1, b1, w2, b2,
                              lag, lab, logw, lob, rw0, rb0, rw1, rb1);
    merge_kernel<<<(512*512*32 + 255)/256, 256>>>(attnw, out);
}

// round 5
// speedup vs baseline: 1.1259x; 1.0562x over previous
#include <cuda_runtime.h>
#include <math.h>

#define NSC   48
#define RMAX  11
#define NCTA  (3*NSC)
#define T     384

#define GW0_F4 (76*64)    // 4864 float4 per scale
#define GW1_F4 (128*64)   // 8192 float4 per scale
#define DYN_SMEM ((GW0_F4 + GW1_F4) * 16)   // 208,896 bytes

__device__ float4 g_gw0p[3*GW0_F4];
__device__ float4 g_gw1p[3*GW1_F4];
__device__ float  g_Wa[6*64*64];
__device__ float  g_ba[6*64];
__device__ float  g_outs[3ull*512*512*64];

__device__ __forceinline__ float sigmf(float v){
    return __fdividef(1.0f, 1.0f + __expf(-v));
}
__device__ __forceinline__ float tanhfast(float v){
    return 1.0f - __fdividef(2.0f, __expf(2.0f*v) + 1.0f);
}

__global__ void pack_gw_kernel(const float* __restrict__ gw0, const float* __restrict__ gw1){
    int i = blockIdx.x*blockDim.x + threadIdx.x;
    float* p0 = (float*)g_gw0p;
    float* p1 = (float*)g_gw1p;
    if (i < 3*76*256){
        int s = i/(76*256), rem = i%(76*256), k = rem/256, j = rem%256;
        p0[(s*76 + k)*256 + ((j&63)<<2) + (j>>6)] = gw0[i];
    }
    if (i < 3*128*256){
        int s = i/(128*256), rem = i%(128*256), k = rem/256, j = rem%256;
        p1[(s*128 + k)*256 + ((j&63)<<2) + (j>>6)] = gw1[i];
    }
}

__global__ void compute_wa_kernel(const float* __restrict__ mi_w, const float* __restrict__ mi_b,
                                  const float* __restrict__ mo_w, const float* __restrict__ mo_b){
    int sl = blockIdx.x;
    const float* miw = mi_w + (size_t)sl*64*192;
    const float* mow = mo_w + (size_t)sl*64*64;
    for (int idx = threadIdx.x; idx < 64*64; idx += blockDim.x){
        int k = idx>>6, n = idx&63;
        float acc = 0.f;
        #pragma unroll 8
        for (int j=0;j<64;j++) acc += miw[k*192 + 128 + j] * mow[j*64 + n];
        g_Wa[sl*4096 + k*64 + n] = acc;
    }
    if (threadIdx.x < 64){
        int n = threadIdx.x;
        float acc = mo_b[sl*64 + n];
        #pragma unroll 8
        for (int j=0;j<64;j++) acc += mi_b[sl*192 + 128 + j] * mow[j*64 + n];
        g_ba[sl*64 + n] = acc;
    }
}

__global__ void __launch_bounds__(T, 1) xlstm_kernel(
    const float* __restrict__ x,
    const float* __restrict__ gb0, const float* __restrict__ gb1,
    const float* __restrict__ w1,  const float* __restrict__ b1,
    const float* __restrict__ w2,  const float* __restrict__ b2,
    const float* __restrict__ lag, const float* __restrict__ lab,
    const float* __restrict__ logw,const float* __restrict__ lob,
    const float* __restrict__ rw0, const float* __restrict__ rb0,
    const float* __restrict__ rw1, const float* __restrict__ rb1)
{
    const int cta = blockIdx.x;
    const int s   = cta / NSC;
    const int ci  = cta % NSC;
    const int base  = (ci < 32) ? ci*11 : 352 + (ci-32)*10;
    const int nrows = (ci < 32) ? 11 : 10;
    const int tid  = threadIdx.x;
    const int m    = tid & 63;
    const int rg   = tid >> 6;     // 0..5
    const int lane = tid & 31;
    const int wrp  = tid >> 5;     // 0..11
    const int n2   = tid & 127;
    const int rg2  = tid >> 7;     // 0..2

    // ---- dynamic smem: resident packed gate weights ----
    extern __shared__ float4 dynsm[];
    float4* s_gw0 = dynsm;              // 4864 float4
    float4* s_gw1 = dynsm + GW0_F4;     // 8192 float4
    {
        const float4* g0 = g_gw0p + (size_t)s*GW0_F4;
        const float4* g1 = g_gw1p + (size_t)s*GW1_F4;
        for (int i=tid;i<GW0_F4;i+=T) s_gw0[i] = g0[i];
        for (int i=tid;i<GW1_F4;i+=T) s_gw1[i] = g1[i];
    }

    __shared__ float sh_h0[RMAX][64], sh_h1[RMAX][64];
    __shared__ float sh_x[RMAX][12];
    __shared__ float sh_hy[RMAX][64];      // aliased: ht (gates->a) then y (t2->ln)
    __shared__ float sh_a[RMAX][64];
    __shared__ float sh_t1[RMAX][128];
    __shared__ float sh_inp[RMAX][64];
    __shared__ float sh_stat[RMAX][2];

    for (int i = tid; i < RMAX*64; i += T){ ((float*)sh_h0)[i] = 0.f; ((float*)sh_h1)[i] = 0.f; }

    // ---- per-thread biases in registers ----
    const float r_gb0f = gb0[s*256 + m],     r_gb0i = gb0[s*256 + 64 + m];
    const float r_gb0g = gb0[s*256 + 128+m], r_gb0o = gb0[s*256 + 192 + m];
    const float r_gb1f = gb1[s*256 + m],     r_gb1i = gb1[s*256 + 64 + m];
    const float r_gb1g = gb1[s*256 + 128+m], r_gb1o = gb1[s*256 + 192 + m];
    const float r_b1_0 = b1[(s*2+0)*128 + n2], r_b1_1 = b1[(s*2+1)*128 + n2];
    const float r_b2_0 = b2[(s*2+0)*64 + m],   r_b2_1 = b2[(s*2+1)*64 + m];
    const float r_ba_0 = g_ba[(s*2+0)*64 + m], r_ba_1 = g_ba[(s*2+1)*64 + m];
    const float r_lag0 = lag[(s*2+0)*64+m],  r_lag1 = lag[(s*2+1)*64+m];
    const float r_lab0 = lab[(s*2+0)*64+m],  r_lab1 = lab[(s*2+1)*64+m];
    const float r_log0 = logw[(s*2+0)*64+m], r_log1 = logw[(s*2+1)*64+m];
    const float r_lob0 = lob[(s*2+0)*64+m],  r_lob1 = lob[(s*2+1)*64+m];
    const float r_rb0  = rb0[s*64+m],        r_rb1  = rb1[s*64+m];
    __syncthreads();

    int myr[2]; int nmy = 0;
    #pragma unroll
    for (int q=0;q<2;q++){ int r = rg + 6*q; myr[q] = (r < nrows) ? r : (nrows-1); if (r < nrows) nmy = q+1; }
    int myr2[4]; int nmy2 = 0;
    #pragma unroll
    for (int q=0;q<4;q++){ int r = rg2 + 3*q; myr2[q] = (r < nrows) ? r : (nrows-1); if (r < nrows) nmy2 = q+1; }

    float c0r[2] = {0.f,0.f}, c1r[2] = {0.f,0.f};

    const float* Wa_l0 = g_Wa + (size_t)(s*2+0)*4096;
    const float* Wa_l1 = g_Wa + (size_t)(s*2+1)*4096;
    const float* w1_l0 = w1 + (size_t)(s*2+0)*64*128;
    const float* w1_l1 = w1 + (size_t)(s*2+1)*64*128;
    const float* w2_l0 = w2 + (size_t)(s*2+0)*128*64;
    const float* w2_l1 = w2 + (size_t)(s*2+1)*128*64;
    const float* rw0s  = rw0 + (size_t)s*12*64;
    const float* rw1s  = rw1 + (size_t)s*64*64;

    const int Li  = (s==0) ? 170 : (s==1 ? 512 : 256);
    const int st0 = (s==0) ? 342 : (s==1 ? 0   : 256);
    const float scf = (float)Li / 512.0f;

    float* outbase = g_outs + ((size_t)s*512 + base)*512*64;

    auto ln_pass = [&](){
        if (wrp < nrows){
            int r = wrp;
            float v0 = sh_hy[r][lane], v1 = sh_hy[r][lane+32];
            float sm = v0 + v1, sq = v0*v0 + v1*v1;
            #pragma unroll
            for (int o=16;o;o>>=1){
                sm += __shfl_xor_sync(0xffffffffu, sm, o);
                sq += __shfl_xor_sync(0xffffffffu, sq, o);
            }
            if (lane == 0){
                float mean = sm * 0.015625f;
                float var  = sq * 0.015625f - mean*mean;
                sh_stat[r][0] = mean;
                sh_stat[r][1] = rsqrtf(var + 1e-5f);
            }
        }
    };

    auto attn_ff_ln = [&](const float* Wap, const float* w1p, const float* w2p,
                          float (*hstate)[64], float* hn_out,
                          float ba_r, float b1_r, float b2_r,
                          float lag_r, float lab_r, float log_r, float lob_r){
        // a = ht @ Wa + ba   (reads sh_hy as ht)
        {
            float aa[2];
            #pragma unroll
            for (int q=0;q<2;q++) aa[q] = ba_r;
            #pragma unroll 8
            for (int k=0;k<64;k++){
                float wv = Wap[k*64 + m];
                #pragma unroll
                for (int q=0;q<2;q++) aa[q] += sh_hy[myr[q]][k] * wv;
            }
            #pragma unroll
            for (int q=0;q<2;q++) if (q < nmy) sh_a[myr[q]][m] = aa[q];
        }
        __syncthreads();
        // t1 = gelu(a @ w1 + b1)
        {
            float ta[4];
            #pragma unroll
            for (int q=0;q<4;q++) ta[q] = b1_r;
            #pragma unroll 8
            for (int k=0;k<64;k++){
                float wv = w1p[k*128 + n2];
                #pragma unroll
                for (int q=0;q<4;q++) ta[q] += sh_a[myr2[q]][k] * wv;
            }
            #pragma unroll
            for (int q=0;q<4;q++){
                float v = ta[q];
                float ge = 0.5f * v * (1.0f + erff(v * 0.7071067811865475f));
                if (q < nmy2) sh_t1[myr2[q]][n2] = ge;
            }
        }
        __syncthreads();
        // y = t1 @ w2 + b2  (write into sh_hy; ht is dead now)
        {
            float ta[2];
            #pragma unroll
            for (int q=0;q<2;q++) ta[q] = b2_r;
            #pragma unroll 8
            for (int k=0;k<128;k++){
                float wv = w2p[k*64 + m];
                #pragma unroll
                for (int q=0;q<2;q++) ta[q] += sh_t1[myr[q]][k] * wv;
            }
            #pragma unroll
            for (int q=0;q<2;q++) if (q < nmy) sh_hy[myr[q]][m] = ta[q];
        }
        __syncthreads();
        ln_pass();
        __syncthreads();
        #pragma unroll
        for (int q=0;q<2;q++){
            int r = myr[q];
            float v  = sh_hy[r][m];
            float ln = (v - sh_stat[r][0]) * sh_stat[r][1] * lag_r + lab_r;
            float yv = ln + hstate[r][m];
            if (q < nmy) sh_hy[r][m] = yv;
        }
        __syncthreads();
        ln_pass();
        __syncthreads();
        #pragma unroll
        for (int q=0;q<2;q++){
            int r = myr[q];
            float yv = sh_hy[r][m];
            float hn = (yv - sh_stat[r][0]) * sh_stat[r][1] * log_r + lob_r;
            hn_out[q] = hn;
            if (q < nmy) hstate[r][m] = hn;
        }
    };

    for (int t=0; t<512; t++){
        float srcf = fmaxf((t + 0.5f) * scf - 0.5f, 0.0f);
        int i0 = (int)srcf;
        if (i0 > Li-1) i0 = Li-1;
        int i1 = min(i0+1, Li-1);
        float wu = srcf - (float)i0;
        if (tid < nrows*12){
            int r = tid/12, k = tid%12;
            const float* xb = x + ((size_t)(base+r)*512 + st0)*12;
            float v0 = xb[i0*12 + k], v1 = xb[i1*12 + k];
            sh_x[r][k] = v0*(1.0f - wu) + v1*wu;
        }
        __syncthreads();

        // ---- layer 0 gates (weights from smem) ----
        {
            float af[2], ai[2], ag[2], ao[2];
            #pragma unroll
            for (int q=0;q<2;q++){ af[q]=r_gb0f; ai[q]=r_gb0i; ag[q]=r_gb0g; ao[q]=r_gb0o; }
            #pragma unroll
            for (int k=0;k<12;k++){
                float4 wv = s_gw0[k*64 + m];
                #pragma unroll
                for (int q=0;q<2;q++){
                    float z = sh_x[myr[q]][k];
                    af[q] += z*wv.x; ai[q] += z*wv.y; ag[q] += z*wv.z; ao[q] += z*wv.w;
                }
            }
            #pragma unroll 8
            for (int k=0;k<64;k++){
                float4 wv = s_gw0[(12+k)*64 + m];
                #pragma unroll
                for (int q=0;q<2;q++){
                    float z = sh_h0[myr[q]][k];
                    af[q] += z*wv.x; ai[q] += z*wv.y; ag[q] += z*wv.z; ao[q] += z*wv.w;
                }
            }
            #pragma unroll
            for (int q=0;q<2;q++){
                float cn = sigmf(af[q])*c0r[q] + sigmf(ai[q])*tanhfast(ag[q]);
                float ht = sigmf(ao[q])*tanhfast(cn);
                if (q < nmy){ c0r[q] = cn; sh_hy[myr[q]][m] = ht; }
            }
        }
        __syncthreads();

        float h0n[2];
        attn_ff_ln(Wa_l0, w1_l0, w2_l0, sh_h0, h0n,
                   r_ba_0, r_b1_0, r_b2_0, r_lag0, r_lab0, r_log0, r_lob0);

        #pragma unroll
        for (int q=0;q<2;q++){
            int r = myr[q];
            float acc = h0n[q] + r_rb0;
            #pragma unroll
            for (int k=0;k<12;k++) acc += sh_x[r][k] * rw0s[k*64 + m];
            if (q < nmy) sh_inp[r][m] = acc;
        }
        __syncthreads();

        // ---- layer 1 gates (weights from smem) ----
        {
            float af[2], ai[2], ag[2], ao[2];
            #pragma unroll
            for (int q=0;q<2;q++){ af[q]=r_gb1f; ai[q]=r_gb1i; ag[q]=r_gb1g; ao[q]=r_gb1o; }
            #pragma unroll 8
            for (int k=0;k<64;k++){
                float4 wv = s_gw1[k*64 + m];
                #pragma unroll
                for (int q=0;q<2;q++){
                    float z = sh_inp[myr[q]][k];
                    af[q] += z*wv.x; ai[q] += z*wv.y; ag[q] += z*wv.z; ao[q] += z*wv.w;
                }
            }
            #pragma unroll 8
            for (int k=0;k<64;k++){
                float4 wv = s_gw1[(64+k)*64 + m];
                #pragma unroll
                for (int q=0;q<2;q++){
                    float z = sh_h1[myr[q]][k];
                    af[q] += z*wv.x; ai[q] += z*wv.y; ag[q] += z*wv.z; ao[q] += z*wv.w;
                }
            }
            #pragma unroll
            for (int q=0;q<2;q++){
                float cn = sigmf(af[q])*c1r[q] + sigmf(ai[q])*tanhfast(ag[q]);
                float ht = sigmf(ao[q])*tanhfast(cn);
                if (q < nmy){ c1r[q] = cn; sh_hy[myr[q]][m] = ht; }
            }
        }
        __syncthreads();

        float h1n[2];
        attn_ff_ln(Wa_l1, w1_l1, w2_l1, sh_h1, h1n,
                   r_ba_1, r_b1_1, r_b2_1, r_lag1, r_lab1, r_log1, r_lob1);

        #pragma unroll
        for (int q=0;q<2;q++){
            int r = myr[q];
            float acc = h1n[q] + r_rb1;
            #pragma unroll 8
            for (int k=0;k<64;k++) acc += sh_inp[r][k] * rw1s[k*64 + m];
            if (q < nmy) outbase[((size_t)r*512 + t)*64 + m] = acc;
        }
        __syncthreads();
    }
}

__global__ void merge_kernel(const float* __restrict__ attn_w, float* __restrict__ out){
    int warp = (blockIdx.x*blockDim.x + threadIdx.x) >> 5;
    int lane = threadIdx.x & 31;
    if (warp >= 512*512) return;
    const size_t SS = 512ull*512*64;
    const float* p = g_outs + (size_t)warp*64;
    float aw0 = attn_w[lane], aw1 = attn_w[lane+32];
    float v0[3], v1[3], sc[3];
    #pragma unroll
    for (int si=0; si<3; si++){
        v0[si] = p[si*SS + lane];
        v1[si] = p[si*SS + lane + 32];
        float d = v0[si]*aw0 + v1[si]*aw1;
        #pragma unroll
        for (int o=16;o;o>>=1) d += __shfl_xor_sync(0xffffffffu, d, o);
        sc[si] = d;
    }
    float mx = fmaxf(sc[0], fmaxf(sc[1], sc[2]));
    float e0 = __expf(sc[0]-mx), e1 = __expf(sc[1]-mx), e2 = __expf(sc[2]-mx);
    float inv = __fdividef(1.0f, e0+e1+e2);
    float wt0 = e0*inv, wt1 = e1*inv, wt2 = e2*inv;
    out[(size_t)warp*64 + lane]      = v0[0]*wt0 + v0[1]*wt1 + v0[2]*wt2;
    out[(size_t)warp*64 + lane + 32] = v1[0]*wt0 + v1[1]*wt1 + v1[2]*wt2;
}

extern "C" void kernel_launch(void* const* d_in, const int* in_sizes, int n_in,
                              void* d_out, int out_size){
    const float* x     = (const float*)d_in[0];
    const float* gw0   = (const float*)d_in[1];
    const float* gb0   = (const float*)d_in[2];
    const float* gw1   = (const float*)d_in[3];
    const float* gb1   = (const float*)d_in[4];
    const float* mi_w  = (const float*)d_in[5];
    const float* mi_b  = (const float*)d_in[6];
    const float* mo_w  = (const float*)d_in[7];
    const float* mo_b  = (const float*)d_in[8];
    const float* w1    = (const float*)d_in[9];
    const float* b1    = (const float*)d_in[10];
    const float* w2    = (const float*)d_in[11];
    const float* b2    = (const float*)d_in[12];
    const float* lag   = (const float*)d_in[13];
    const float* lab   = (const float*)d_in[14];
    const float* logw  = (const float*)d_in[15];
    const float* lob   = (const float*)d_in[16];
    const float* rw0   = (const float*)d_in[17];
    const float* rb0   = (const float*)d_in[18];
    const float* rw1   = (const float*)d_in[19];
    const float* rb1   = (const float*)d_in[20];
    const float* attnw = (const float*)d_in[21];
    float* out = (float*)d_out;

    static int smem_set = 0;
    if (!smem_set){
        cudaFuncSetAttribute(xlstm_kernel, cudaFuncAttributeMaxDynamicSharedMemorySize, DYN_SMEM);
        smem_set = 1;
    }

    pack_gw_kernel<<<(3*128*256 + 255)/256, 256>>>(gw0, gw1);
    compute_wa_kernel<<<6, 256>>>(mi_w, mi_b, mo_w, mo_b);
    xlstm_kernel<<<NCTA, T, DYN_SMEM>>>(x, gb0, gb1, w1, b1, w2, b2,
                                        lag, lab, logw, lob, rw0, rb0, rw1, rb1);
    merge_kernel<<<(512*512*32 + 255)/256, 256>>>(attnw, out);
}

// round 7
// speedup vs baseline: 1.4446x; 1.2830x over previous
#include <cuda_runtime.h>
#include <math.h>

#define NSC   48
#define RMAX  11
#define NCTA  (3*NSC)
#define T     384

#define GW0_F4 (76*64)     // 4864 float4 per scale (both chunks)
#define GW0_C  2432        // f4 per chunk (38 k-rows)
#define GW1_F4 (128*64)    // 8192 float4 per scale
#define PAN_F4 2560        // 40KB panel buffer
#define DYN_SMEM ((GW1_F4 + PAN_F4) * 16)   // 172,032 bytes

__device__ float4 g_gw0p[3*GW0_F4];
__device__ float4 g_gw1p[3*GW1_F4];
__device__ float  g_Wa[6*64*64];
__device__ float  g_ba[6*64];
__device__ float  g_outs[3ull*512*512*64];

__device__ __forceinline__ float sigmf(float v){
    return __fdividef(1.0f, 1.0f + __expf(-v));
}
__device__ __forceinline__ float tanhfast(float v){
    return 1.0f - __fdividef(2.0f, __expf(2.0f*v) + 1.0f);
}

template<int N>
__device__ __forceinline__ void cpyp(float4* d, const float4* __restrict__ s, int tid){
    #pragma unroll
    for (int i = 0; i < (N + T - 1)/T; i++){
        int j = tid + i*T;
        if (j < N) d[j] = s[j];
    }
}

__global__ void pack_gw_kernel(const float* __restrict__ gw0, const float* __restrict__ gw1){
    int i = blockIdx.x*blockDim.x + threadIdx.x;
    float* p0 = (float*)g_gw0p;
    float* p1 = (float*)g_gw1p;
    if (i < 3*76*256){
        int s = i/(76*256), rem = i%(76*256), k = rem/256, j = rem%256;
        p0[(s*76 + k)*256 + ((j&63)<<2) + (j>>6)] = gw0[i];
    }
    if (i < 3*128*256){
        int s = i/(128*256), rem = i%(128*256), k = rem/256, j = rem%256;
        p1[(s*128 + k)*256 + ((j&63)<<2) + (j>>6)] = gw1[i];
    }
}

__global__ void compute_wa_kernel(const float* __restrict__ mi_w, const float* __restrict__ mi_b,
                                  const float* __restrict__ mo_w, const float* __restrict__ mo_b){
    int sl = blockIdx.x;
    const float* miw = mi_w + (size_t)sl*64*192;
    const float* mow = mo_w + (size_t)sl*64*64;
    for (int idx = threadIdx.x; idx < 64*64; idx += blockDim.x){
        int k = idx>>6, n = idx&63;
        float acc = 0.f;
        #pragma unroll 8
        for (int j=0;j<64;j++) acc += miw[k*192 + 128 + j] * mow[j*64 + n];
        g_Wa[sl*4096 + k*64 + n] = acc;
    }
    if (threadIdx.x < 64){
        int n = threadIdx.x;
        float acc = mo_b[sl*64 + n];
        #pragma unroll 8
        for (int j=0;j<64;j++) acc += mi_b[sl*192 + 128 + j] * mow[j*64 + n];
        g_ba[sl*64 + n] = acc;
    }
}

__global__ void __launch_bounds__(T, 1) xlstm_kernel(
    const float* __restrict__ x,
    const float* __restrict__ gb0, const float* __restrict__ gb1,
    const float* __restrict__ w1,  const float* __restrict__ b1,
    const float* __restrict__ w2,  const float* __restrict__ b2,
    const float* __restrict__ lag, const float* __restrict__ lab,
    const float* __restrict__ logw,const float* __restrict__ lob,
    const float* __restrict__ rw0, const float* __restrict__ rb0,
    const float* __restrict__ rw1, const float* __restrict__ rb1)
{
    const int cta = blockIdx.x;
    const int s   = cta / NSC;
    const int ci  = cta % NSC;
    const int base  = (ci < 32) ? ci*11 : 352 + (ci-32)*10;
    const int nrows = (ci < 32) ? 11 : 10;
    const int tid  = threadIdx.x;
    const int m    = tid & 63;      // old mapping: feature col
    const int rg   = tid >> 6;      // 0..5
    const int lane = tid & 31;
    const int wrp  = tid >> 5;      // 0..11
    // new mapping (2 cols / thread)
    const int cg   = tid & 31;      // col-pair within 64-wide
    const int m2   = cg*2;
    const int cgf  = tid & 63;      // col-pair within 128-wide
    const int n2b  = cgf*2;
    const int rgf  = tid >> 6;      // 0..5 (row group for ff1)

    extern __shared__ float4 dynsm[];
    float4* s_gw1 = dynsm;               // 8192 f4 resident
    float4* pan4  = dynsm + GW1_F4;      // 2560 f4 panel
    float2* pan2  = (float2*)pan4;

    __shared__ __align__(16) float sh_h0[RMAX][64], sh_h1[RMAX][64];
    __shared__ __align__(16) float sh_x[RMAX][12];
    __shared__ __align__(16) float sh_hy[RMAX][64];
    __shared__ __align__(16) float sh_a[RMAX][64];
    __shared__ __align__(16) float sh_t1[RMAX][128];
    __shared__ __align__(16) float sh_inp[RMAX][64];
    __shared__ float sh_stat[RMAX][2];
    __shared__ __align__(16) float sb_ba[2][64];
    __shared__ __align__(16) float sb_b1[2][128];
    __shared__ __align__(16) float sb_b2[2][64];
    __shared__ __align__(16) float sb_rb1[64];
    __shared__ __align__(16) float s_rw0[12*64];
    __shared__ __align__(16) float s_rw1[64*64];

    // ---- resident loads ----
    {
        const float4* g1 = g_gw1p + (size_t)s*GW1_F4;
        for (int i=tid;i<GW1_F4;i+=T) s_gw1[i] = g1[i];
        const float* rw1s = rw1 + (size_t)s*4096;
        for (int i=tid;i<4096;i+=T) s_rw1[i] = rw1s[i];
        const float* rw0s = rw0 + (size_t)s*768;
        for (int i=tid;i<768;i+=T) s_rw0[i] = rw0s[i];   // FIXED: full 768 loaded
        for (int i = tid; i < RMAX*64; i += T){ ((float*)sh_h0)[i] = 0.f; ((float*)sh_h1)[i] = 0.f; }
        if (tid < 128){
            sb_b1[0][tid] = b1[(s*2+0)*128 + tid];
            sb_b1[1][tid] = b1[(s*2+1)*128 + tid];
        }
        if (tid < 64){
            sb_ba[0][tid] = g_ba[(s*2+0)*64 + tid];
            sb_ba[1][tid] = g_ba[(s*2+1)*64 + tid];
            sb_b2[0][tid] = b2[(s*2+0)*64 + tid];
            sb_b2[1][tid] = b2[(s*2+1)*64 + tid];
            sb_rb1[tid]   = rb1[s*64 + tid];
        }
    }
    // per-thread reg params (old mapping)
    const float r_gb0f = gb0[s*256 + m],     r_gb0i = gb0[s*256 + 64 + m];
    const float r_gb0g = gb0[s*256 + 128+m], r_gb0o = gb0[s*256 + 192 + m];
    const float r_gb1f = gb1[s*256 + m],     r_gb1i = gb1[s*256 + 64 + m];
    const float r_gb1g = gb1[s*256 + 128+m], r_gb1o = gb1[s*256 + 192 + m];
    const float r_lag0 = lag[(s*2+0)*64+m],  r_lag1 = lag[(s*2+1)*64+m];
    const float r_lab0 = lab[(s*2+0)*64+m],  r_lab1 = lab[(s*2+1)*64+m];
    const float r_log0 = logw[(s*2+0)*64+m], r_log1 = logw[(s*2+1)*64+m];
    const float r_lob0 = lob[(s*2+0)*64+m],  r_lob1 = lob[(s*2+1)*64+m];
    const float r_rb0  = rb0[s*64+m];
    __syncthreads();

    int myr[2]; int nmy = 0;
    #pragma unroll
    for (int q=0;q<2;q++){ int r = rg + 6*q; myr[q] = (r < nrows) ? r : (nrows-1); if (r < nrows) nmy = q+1; }
    // ff1 rows
    const int rA = rgf;
    const int rBr = rgf + 6;
    const bool hasB = (rBr < nrows);
    const int rB = hasB ? rBr : 0;

    float c0r[2] = {0.f,0.f}, c1r[2] = {0.f,0.f};

    const float4* gw0g  = g_gw0p + (size_t)s*GW0_F4;
    const float4* Wa0_4 = (const float4*)g_Wa + (size_t)(s*2+0)*1024;
    const float4* Wa1_4 = (const float4*)g_Wa + (size_t)(s*2+1)*1024;
    const float4* w10_4 = (const float4*)(w1 + (size_t)(s*2+0)*8192);
    const float4* w11_4 = (const float4*)(w1 + (size_t)(s*2+1)*8192);
    const float4* w20_4 = (const float4*)(w2 + (size_t)(s*2+0)*8192);
    const float4* w21_4 = (const float4*)(w2 + (size_t)(s*2+1)*8192);

    const int Li  = (s==0) ? 170 : (s==1 ? 512 : 256);
    const int st0 = (s==0) ? 342 : (s==1 ? 0   : 256);
    const float scf = (float)Li / 512.0f;

    float* outbase = g_outs + ((size_t)s*512 + base)*512*64;

    auto ln_pass = [&](){
        if (wrp < nrows){
            int r = wrp;
            float v0 = sh_hy[r][lane], v1 = sh_hy[r][lane+32];
            float sm = v0 + v1, sq = v0*v0 + v1*v1;
            #pragma unroll
            for (int o=16;o;o>>=1){
                sm += __shfl_xor_sync(0xffffffffu, sm, o);
                sq += __shfl_xor_sync(0xffffffffu, sq, o);
            }
            if (lane == 0){
                float mean = sm * 0.015625f;
                float var  = sq * 0.015625f - mean*mean;
                sh_stat[r][0] = mean;
                sh_stat[r][1] = rsqrtf(var + 1e-5f);
            }
        }
    };

    auto attn_stage = [&](int l){
        if (wrp < nrows){
            int r = wrp;
            float a0 = sb_ba[l][m2], a1 = sb_ba[l][m2+1];
            #pragma unroll 8
            for (int k=0;k<64;k++){
                float z = sh_hy[r][k];
                float2 wv = pan2[k*32 + cg];
                a0 += z*wv.x; a1 += z*wv.y;
            }
            *(float2*)&sh_a[r][m2] = make_float2(a0, a1);
        }
    };
    auto ff1_stage = [&](int l){
        float t00 = sb_b1[l][n2b], t01 = sb_b1[l][n2b+1];
        float t10 = t00, t11 = t01;
        #pragma unroll 8
        for (int k=0;k<64;k++){
            float z0 = sh_a[rA][k];
            float z1 = sh_a[rB][k];
            float2 wv = pan2[k*64 + cgf];
            t00 += z0*wv.x; t01 += z0*wv.y;
            t10 += z1*wv.x; t11 += z1*wv.y;
        }
        const float c = 0.7071067811865475f;
        float g00 = 0.5f*t00*(1.0f + erff(t00*c));
        float g01 = 0.5f*t01*(1.0f + erff(t01*c));
        *(float2*)&sh_t1[rA][n2b] = make_float2(g00, g01);
        if (hasB){
            float g10 = 0.5f*t10*(1.0f + erff(t10*c));
            float g11 = 0.5f*t11*(1.0f + erff(t11*c));
            *(float2*)&sh_t1[rB][n2b] = make_float2(g10, g11);
        }
    };
    auto ff2_stage = [&](int l){
        if (wrp < nrows){
            int r = wrp;
            float a0 = sb_b2[l][m2], a1 = sb_b2[l][m2+1];
            #pragma unroll 8
            for (int k=0;k<128;k++){
                float z = sh_t1[r][k];
                float2 wv = pan2[k*32 + cg];
                a0 += z*wv.x; a1 += z*wv.y;
            }
            *(float2*)&sh_hy[r][m2] = make_float2(a0, a1);
        }
    };
    auto ln_chain = [&](float (*hstate)[64], float* hn_out,
                        float lag_r, float lab_r, float log_r, float lob_r){
        ln_pass();
        __syncthreads();
        #pragma unroll
        for (int q=0;q<2;q++){
            int r = myr[q];
            float v  = sh_hy[r][m];
            float ln = (v - sh_stat[r][0]) * sh_stat[r][1] * lag_r + lab_r;
            float yv = ln + hstate[r][m];
            if (q < nmy) sh_hy[r][m] = yv;
        }
        __syncthreads();
        ln_pass();
        __syncthreads();
        #pragma unroll
        for (int q=0;q<2;q++){
            int r = myr[q];
            float yv = sh_hy[r][m];
            float hn = (yv - sh_stat[r][0]) * sh_stat[r][1] * log_r + lob_r;
            hn_out[q] = hn;
            if (q < nmy) hstate[r][m] = hn;
        }
    };

    for (int t=0; t<512; t++){
        // ---- stage gw0 chunk A + x upsample ----
        cpyp<GW0_C>(pan4, gw0g, tid);
        {
            float srcf = fmaxf((t + 0.5f) * scf - 0.5f, 0.0f);
            int i0 = (int)srcf;
            if (i0 > Li-1) i0 = Li-1;
            int i1 = min(i0+1, Li-1);
            float wu = srcf - (float)i0;
            if (tid < nrows*12){
                int r = tid/12, k = tid%12;
                const float* xb = x + ((size_t)(base+r)*512 + st0)*12;
                float v0 = xb[i0*12 + k], v1 = xb[i1*12 + k];
                sh_x[r][k] = v0*(1.0f - wu) + v1*wu;
            }
        }
        __syncthreads();                                   // S1

        // ---- gates layer 0 ----
        float af[2], ai[2], ag[2], ao[2];
        #pragma unroll
        for (int q=0;q<2;q++){ af[q]=r_gb0f; ai[q]=r_gb0i; ag[q]=r_gb0g; ao[q]=r_gb0o; }
        #pragma unroll
        for (int k=0;k<12;k++){
            float4 wv = pan4[k*64 + m];
            #pragma unroll
            for (int q=0;q<2;q++){
                float z = sh_x[myr[q]][k];
                af[q] += z*wv.x; ai[q] += z*wv.y; ag[q] += z*wv.z; ao[q] += z*wv.w;
            }
        }
        #pragma unroll 8
        for (int k=12;k<38;k++){
            float4 wv = pan4[k*64 + m];
            #pragma unroll
            for (int q=0;q<2;q++){
                float z = sh_h0[myr[q]][k-12];
                af[q] += z*wv.x; ai[q] += z*wv.y; ag[q] += z*wv.z; ao[q] += z*wv.w;
            }
        }
        __syncthreads();                                   // S2
        cpyp<GW0_C>(pan4, gw0g + GW0_C, tid);
        __syncthreads();                                   // S3
        #pragma unroll 8
        for (int k=38;k<76;k++){
            float4 wv = pan4[(k-38)*64 + m];
            #pragma unroll
            for (int q=0;q<2;q++){
                float z = sh_h0[myr[q]][k-12];
                af[q] += z*wv.x; ai[q] += z*wv.y; ag[q] += z*wv.z; ao[q] += z*wv.w;
            }
        }
        #pragma unroll
        for (int q=0;q<2;q++){
            float cn = sigmf(af[q])*c0r[q] + sigmf(ai[q])*tanhfast(ag[q]);
            float ht = sigmf(ao[q])*tanhfast(cn);
            if (q < nmy){ c0r[q] = cn; sh_hy[myr[q]][m] = ht; }
        }
        __syncthreads();                                   // S4
        cpyp<1024>(pan4, Wa0_4, tid);
        __syncthreads();                                   // S5
        attn_stage(0);
        __syncthreads();                                   // S6
        cpyp<2048>(pan4, w10_4, tid);
        __syncthreads();                                   // S7
        ff1_stage(0);
        __syncthreads();                                   // S8
        cpyp<2048>(pan4, w20_4, tid);
        __syncthreads();                                   // S9
        ff2_stage(0);
        __syncthreads();                                   // S10
        float h0n[2];
        ln_chain(sh_h0, h0n, r_lag0, r_lab0, r_log0, r_lob0);
        #pragma unroll
        for (int q=0;q<2;q++){
            int r = myr[q];
            float acc = h0n[q] + r_rb0;
            #pragma unroll
            for (int k=0;k<12;k++) acc += sh_x[r][k] * s_rw0[k*64 + m];
            if (q < nmy) sh_inp[r][m] = acc;
        }
        __syncthreads();                                   // S14

        // ---- gates layer 1 (resident) + prefetch Wa1 panel ----
        cpyp<1024>(pan4, Wa1_4, tid);
        {
            float bf[2], bi[2], bg[2], bo[2];
            #pragma unroll
            for (int q=0;q<2;q++){ bf[q]=r_gb1f; bi[q]=r_gb1i; bg[q]=r_gb1g; bo[q]=r_gb1o; }
            #pragma unroll 8
            for (int k=0;k<64;k++){
                float4 wv = s_gw1[k*64 + m];
                #pragma unroll
                for (int q=0;q<2;q++){
                    float z = sh_inp[myr[q]][k];
                    bf[q] += z*wv.x; bi[q] += z*wv.y; bg[q] += z*wv.z; bo[q] += z*wv.w;
                }
            }
            #pragma unroll 8
            for (int k=0;k<64;k++){
                float4 wv = s_gw1[(64+k)*64 + m];
                #pragma unroll
                for (int q=0;q<2;q++){
                    float z = sh_h1[myr[q]][k];
                    bf[q] += z*wv.x; bi[q] += z*wv.y; bg[q] += z*wv.z; bo[q] += z*wv.w;
                }
            }
            #pragma unroll
            for (int q=0;q<2;q++){
                float cn = sigmf(bf[q])*c1r[q] + sigmf(bi[q])*tanhfast(bg[q]);
                float ht = sigmf(bo[q])*tanhfast(cn);
                if (q < nmy){ c1r[q] = cn; sh_hy[myr[q]][m] = ht; }
            }
        }
        __syncthreads();                                   // S15
        attn_stage(1);
        __syncthreads();                                   // S16
        cpyp<2048>(pan4, w11_4, tid);
        __syncthreads();                                   // S17
        ff1_stage(1);
        __syncthreads();                                   // S18
        cpyp<2048>(pan4, w21_4, tid);
        __syncthreads();                                   // S19
        ff2_stage(1);
        __syncthreads();                                   // S20
        float h1n[2];
        ln_chain(sh_h1, h1n, r_lag1, r_lab1, r_log1, r_lob1);
        __syncthreads();                                   // S24

        // ---- out = h1_new + inp@rw1 + rb1 (new mapping) ----
        if (wrp < nrows){
            int r = wrp;
            float o0 = sh_h1[r][m2]   + sb_rb1[m2];
            float o1 = sh_h1[r][m2+1] + sb_rb1[m2+1];
            const float2* rw12 = (const float2*)s_rw1;
            #pragma unroll 8
            for (int k=0;k<64;k++){
                float z = sh_inp[r][k];
                float2 wv = rw12[k*32 + cg];
                o0 += z*wv.x; o1 += z*wv.y;
            }
            ((float2*)(outbase + ((size_t)r*512 + t)*64))[cg] = make_float2(o0, o1);
        }
        __syncthreads();                                   // S25
    }
}

__global__ void merge_kernel(const float* __restrict__ attn_w, float* __restrict__ out){
    int warp = (blockIdx.x*blockDim.x + threadIdx.x) >> 5;
    int lane = threadIdx.x & 31;
    if (warp >= 512*512) return;
    const size_t SS = 512ull*512*64;
    const float* p = g_outs + (size_t)warp*64;
    float aw0 = attn_w[lane], aw1 = attn_w[lane+32];
    float v0[3], v1[3], sc[3];
    #pragma unroll
    for (int si=0; si<3; si++){
        v0[si] = p[si*SS + lane];
        v1[si] = p[si*SS + lane + 32];
        float d = v0[si]*aw0 + v1[si]*aw1;
        #pragma unroll
        for (int o=16;o;o>>=1) d += __shfl_xor_sync(0xffffffffu, d, o);
        sc[si] = d;
    }
    float mx = fmaxf(sc[0], fmaxf(sc[1], sc[2]));
    float e0 = __expf(sc[0]-mx), e1 = __expf(sc[1]-mx), e2 = __expf(sc[2]-mx);
    float inv = __fdividef(1.0f, e0+e1+e2);
    float wt0 = e0*inv, wt1 = e1*inv, wt2 = e2*inv;
    out[(size_t)warp*64 + lane]      = v0[0]*wt0 + v0[1]*wt1 + v0[2]*wt2;
    out[(size_t)warp*64 + lane + 32] = v1[0]*wt0 + v1[1]*wt1 + v1[2]*wt2;
}

extern "C" void kernel_launch(void* const* d_in, const int* in_sizes, int n_in,
                              void* d_out, int out_size){
    const float* x     = (const float*)d_in[0];
    const float* gw0   = (const float*)d_in[1];
    const float* gb0   = (const float*)d_in[2];
    const float* gw1   = (const float*)d_in[3];
    const float* gb1   = (const float*)d_in[4];
    const float* mi_w  = (const float*)d_in[5];
    const float* mi_b  = (const float*)d_in[6];
    const float* mo_w  = (const float*)d_in[7];
    const float* mo_b  = (const float*)d_in[8];
    const float* w1    = (const float*)d_in[9];
    const float* b1    = (const float*)d_in[10];
    const float* w2    = (const float*)d_in[11];
    const float* b2    = (const float*)d_in[12];
    const float* lag   = (const float*)d_in[13];
    const float* lab   = (const float*)d_in[14];
    const float* logw  = (const float*)d_in[15];
    const float* lob   = (const float*)d_in[16];
    const float* rw0   = (const float*)d_in[17];
    const float* rb0   = (const float*)d_in[18];
    const float* rw1   = (const float*)d_in[19];
    const float* rb1   = (const float*)d_in[20];
    const float* attnw = (const float*)d_in[21];
    float* out = (float*)d_out;

    static int smem_set = 0;
    if (!smem_set){
        cudaFuncSetAttribute(xlstm_kernel, cudaFuncAttributeMaxDynamicSharedMemorySize, DYN_SMEM);
        smem_set = 1;
    }

    pack_gw_kernel<<<(3*128*256 + 255)/256, 256>>>(gw0, gw1);
    compute_wa_kernel<<<6, 256>>>(mi_w, mi_b, mo_w, mo_b);
    xlstm_kernel<<<NCTA, T, DYN_SMEM>>>(x, gb0, gb1, w1, b1, w2, b2,
                                        lag, lab, logw, lob, rw0, rb0, rw1, rb1);
    merge_kernel<<<(512*512*32 + 255)/256, 256>>>(attnw, out);
}